// round 11
// baseline (speedup 1.0000x reference)
#include <cuda_runtime.h>
#include <math.h>
#include <stddef.h>

#define BB    64
#define TT    1024
#define VOCAB 55
#define EMBED 64
#define HID   128

typedef unsigned long long u64;

__device__ float g_outs[BB * TT * HID];
__device__ float g_q   [BB * TT * HID];
__device__ float g_ctx [BB * TT * HID];
__device__ float g_tab0[VOCAB * HID];
// Cross-SM h0 pipe: 16-deep ring + monotonic flag/credit per batch
__device__ float g_ring[BB][16][HID];
__device__ int   g_flag[BB];
__device__ int   g_cred[BB];

// Packed f32x2 helpers
__device__ __forceinline__ u64 fma2(u64 a, u64 b, u64 c) {
    u64 d; asm("fma.rn.f32x2 %0, %1, %2, %3;" : "=l"(d) : "l"(a), "l"(b), "l"(c));
    return d;
}
__device__ __forceinline__ u64 add2(u64 a, u64 b) {
    u64 d; asm("add.rn.f32x2 %0, %1, %2;" : "=l"(d) : "l"(a), "l"(b));
    return d;
}
__device__ __forceinline__ u64 mul2(u64 a, u64 b) {
    u64 d; asm("mul.rn.f32x2 %0, %1, %2;" : "=l"(d) : "l"(a), "l"(b));
    return d;
}
__device__ __forceinline__ u64 splat2(float v) {
    u64 r; asm("mov.b64 %0, {%1, %1};" : "=l"(r) : "f"(v));
    return r;
}
__device__ __forceinline__ float2 unpack2(u64 v) {
    float lo, hi; asm("mov.b64 {%0, %1}, %2;" : "=f"(lo), "=f"(hi) : "l"(v));
    return make_float2(lo, hi);
}
__device__ __forceinline__ float hadd2(u64 v) {
    float2 p = unpack2(v); return p.x + p.y;
}
__device__ __forceinline__ float tanh_fast(float x) {
    float e = __expf(2.0f * x);
    return 1.0f - __fdividef(2.0f, e + 1.0f);
}

// ---------------------------------------------------------------------------
__global__ void reset_kernel() {
    int t = threadIdx.x;
    if (t < BB) { g_flag[t] = 0; g_cred[t] = 0; }
}

// ---------------------------------------------------------------------------
__global__ void tab0_kernel(const float* __restrict__ emb,
                            const float* __restrict__ w_ih0,
                            const float* __restrict__ b_ih0,
                            const float* __restrict__ b_hh0) {
    __shared__ float es[EMBED];
    int v = blockIdx.x;
    int i = threadIdx.x;
    if (i < EMBED) es[i] = emb[v * EMBED + i];
    __syncthreads();
    float acc = b_ih0[i] + b_hh0[i];
    #pragma unroll
    for (int e = 0; e < EMBED; e++)
        acc += es[e] * w_ih0[i * EMBED + e];
    g_tab0[v * HID + i] = acc;
}

// ---------------------------------------------------------------------------
// RNN: layer0 and layer1 on SEPARATE SMs, joined by a gmem ring through L2.
//   blocks 0..63   (producer): layer0 for batch b = blockIdx.x
//   blocks 64..127 (consumer): layer1 for batch b = blockIdx.x - 64
// 256 threads each: i = t>>1, q = t&1.
//   producer: q-split halves of w_hh0 row i (32 u64 regs), shfl combine.
//   consumer: q=0 -> w_ih1 row i vs h0 slab; q=1 -> w_hh1 row i vs h1.
// Protocol: producer writes slab st to ring slot st&15, threadfence,
// syncthreads, thread0 sets flag=st+1 (volatile). Consumer reads flag at the
// step top (latency hidden under the dot), q=1 half copies slab st+1 into
// smem hbuf via __ldcg after the flag confirms; credit = st+1 released at
// step top (slab st was copied last step). Ring depth 16; the producer is
// intrinsically faster, so it runs ahead and absorbs all sync latency.
// Grid = 128 blocks <= 148 SMs: single wave, co-residency guaranteed.
// ---------------------------------------------------------------------------
__global__ __launch_bounds__(256, 1)
void rnn_kernel(const int*   __restrict__ x,
                const float* __restrict__ w_hh0,
                const float* __restrict__ w_ih1,
                const float* __restrict__ b_ih1,
                const float* __restrict__ w_hh1,
                const float* __restrict__ b_hh1) {
    __shared__ float tab0s[VOCAB * HID];
    __shared__ int   xs[TT];
    __shared__ __align__(16) float h0s[2][HID];   // producer-local
    __shared__ __align__(16) float hbuf[2][HID];  // consumer: incoming h0
    __shared__ __align__(16) float h1s[2][HID];   // consumer-local

    const int role = (blockIdx.x >= BB);
    const int b = blockIdx.x & (BB - 1);
    const int t = threadIdx.x;
    const int i = t >> 1;
    const int q = t & 1;

    volatile int* flagp = &g_flag[b];
    volatile int* credp = &g_cred[b];

    if (!role) {
        // ---------------- producer: layer0 ----------------
        for (int idx = t; idx < VOCAB * HID; idx += 256) tab0s[idx] = g_tab0[idx];
        for (int idx = t; idx < TT;          idx += 256) xs[idx]    = x[b * TT + idx];
        if (t < HID) { h0s[0][t] = 0.f; h0s[1][t] = 0.f; }

        u64 wreg[32];   // w_hh0[i][q*64 .. q*64+63]
        {
            const ulonglong2* wp = (const ulonglong2*)(w_hh0 + i * HID + q * 64);
            #pragma unroll
            for (int m = 0; m < 16; m++) { ulonglong2 v = wp[m]; wreg[2*m] = v.x; wreg[2*m+1] = v.y; }
        }
        __syncthreads();

        #pragma unroll 1
        for (int st = 0; st < TT; st++) {
            int cr = *credp;                         // early read, hidden under dot
            const float tb = tab0s[xs[st] * HID + i];
            const ulonglong2* hp = (const ulonglong2*)(&h0s[(st - 1) & 1][q * 64]);
            u64 a0 = 0, a1 = 0, a2 = 0, a3 = 0;
            #pragma unroll
            for (int m = 0; m < 8; m++) {
                ulonglong2 va = hp[2*m], vb = hp[2*m + 1];
                a0 = fma2(va.x, wreg[4*m],     a0);
                a1 = fma2(va.y, wreg[4*m + 1], a1);
                a2 = fma2(vb.x, wreg[4*m + 2], a2);
                a3 = fma2(vb.y, wreg[4*m + 3], a3);
            }
            float acc = hadd2(add2(add2(a0, a1), add2(a2, a3)));
            acc += __shfl_xor_sync(0xffffffffu, acc, 1);
            float h0n = tanh_fast(acc + tb);
            if (st >= 16) { while (cr < st - 15) cr = *credp; }   // ring credit
            if (!q) {
                h0s[st & 1][i] = h0n;
                g_ring[b][st & 15][i] = h0n;
            }
            __threadfence();                         // slab globally ordered
            __syncthreads();                         // all stores done + smem handoff
            if (t == 0) *flagp = st + 1;             // publish
        }
    } else {
        // ---------------- consumer: layer1 ----------------
        if (t < HID) { h1s[0][t] = 0.f; h1s[1][t] = 0.f; }
        u64 wreg[64];   // q==0: w_ih1 row i; q==1: w_hh1 row i
        {
            const ulonglong2* wp = (const ulonglong2*)((q ? w_hh1 : w_ih1) + i * HID);
            #pragma unroll
            for (int m = 0; m < 32; m++) { ulonglong2 v = wp[m]; wreg[2*m] = v.x; wreg[2*m+1] = v.y; }
        }
        const float c1 = b_ih1[i] + b_hh1[i];

        // prologue: pull slab 0
        {
            int f = *flagp;
            while (f < 1) f = *flagp;
            __threadfence();
            if (t < HID) hbuf[0][t] = __ldcg(&g_ring[b][0][t]);
        }
        __syncthreads();

        float* outp = g_outs + (size_t)b * TT * HID;

        #pragma unroll 1
        for (int st = 0; st < TT; st++) {
            int f = *flagp;                          // early read, hidden under dot
            if (t == 1) *credp = st + 1;             // slabs <= st consumed
            const ulonglong2* sp = (const ulonglong2*)(q ? &h1s[(st + 1) & 1][0]
                                                        : &hbuf[st & 1][0]);
            u64 a0 = 0, a1 = 0, a2 = 0, a3 = 0;
            #pragma unroll
            for (int m = 0; m < 16; m++) {
                ulonglong2 va = sp[2*m], vb = sp[2*m + 1];
                a0 = fma2(va.x, wreg[4*m],     a0);
                a1 = fma2(va.y, wreg[4*m + 1], a1);
                a2 = fma2(vb.x, wreg[4*m + 2], a2);
                a3 = fma2(vb.y, wreg[4*m + 3], a3);
            }
            if (q && st + 1 < TT) {                  // fetch next slab (q=1 half)
                while (f < st + 2) f = *flagp;       // normally already satisfied
                __threadfence();
                hbuf[(st + 1) & 1][i] = __ldcg(&g_ring[b][(st + 1) & 15][i]);
            }
            float acc = hadd2(add2(add2(a0, a1), add2(a2, a3)));
            acc += __shfl_xor_sync(0xffffffffu, acc, 1);
            float h1n = tanh_fast(acc + c1);
            if (!q) {
                h1s[st & 1][i] = h1n;
                outp[st * HID + i] = h1n;
            }
            __syncthreads();                         // hbuf/h1s handoff
        }
    }
}

// ---------------------------------------------------------------------------
// Q projection
// ---------------------------------------------------------------------------
__global__ __launch_bounds__(256, 1)
void q_kernel(const float* __restrict__ attn_w, const float* __restrict__ attn_b) {
    extern __shared__ float smq[];
    float* wt  = smq;                 // [k=128][i stride 132]
    float* ost = smq + 128 * 132;     // [k=128][r stride 68]
    __shared__ float bs[HID];

    const int t = threadIdx.x;
    const int rg = t >> 4, cg = t & 15;
    const size_t rowbase = (size_t)blockIdx.x * 64;

    for (int idx = t; idx < HID * HID; idx += 256) {
        int i = idx >> 7, k = idx & 127;
        wt[k * 132 + i] = attn_w[idx];
    }
    for (int idx = t; idx < 64 * HID; idx += 256) {
        int r = idx >> 7, k = idx & 127;
        ost[k * 68 + r] = g_outs[(rowbase + r) * HID + k];
    }
    if (t < HID) bs[t] = attn_b[t];
    __syncthreads();

    u64 acc[4][4];
    #pragma unroll
    for (int rr = 0; rr < 4; rr++)
        #pragma unroll
        for (int c = 0; c < 4; c++) acc[rr][c] = 0ull;

    #pragma unroll 2
    for (int k = 0; k < HID; k++) {
        float4 q4 = *(const float4*)(ost + k * 68 + rg * 4);
        ulonglong2 w0 = *(const ulonglong2*)(wt + k * 132 + cg * 8);
        ulonglong2 w1 = *(const ulonglong2*)(wt + k * 132 + cg * 8 + 4);
        float qv[4] = {q4.x, q4.y, q4.z, q4.w};
        #pragma unroll
        for (int rr = 0; rr < 4; rr++) {
            u64 qs = splat2(qv[rr]);
            acc[rr][0] = fma2(qs, w0.x, acc[rr][0]);
            acc[rr][1] = fma2(qs, w0.y, acc[rr][1]);
            acc[rr][2] = fma2(qs, w1.x, acc[rr][2]);
            acc[rr][3] = fma2(qs, w1.y, acc[rr][3]);
        }
    }

    #pragma unroll
    for (int rr = 0; rr < 4; rr++) {
        size_t row = rowbase + rg * 4 + rr;
        float o[8];
        #pragma unroll
        for (int c = 0; c < 4; c++) {
            float2 p = unpack2(acc[rr][c]);
            o[2*c]   = p.x + bs[cg * 8 + 2*c];
            o[2*c+1] = p.y + bs[cg * 8 + 2*c + 1];
        }
        *(float4*)(g_q + row * HID + cg * 8)     = make_float4(o[0], o[1], o[2], o[3]);
        *(float4*)(g_q + row * HID + cg * 8 + 4) = make_float4(o[4], o[5], o[6], o[7]);
    }
}

// ---------------------------------------------------------------------------
// Flash attention, 2 CTAs/SM, LPT ordering (round-10 winner, unchanged).
// ---------------------------------------------------------------------------
#define KROW  130
#define KROW2 65

__global__ __launch_bounds__(256, 2)
void attn_kernel() {
    extern __shared__ float sma[];
    float* Qs = sma;                     // [64][130]
    float* Ks = sma + 64 * KROW;         // [64][130]
    float* St = sma + 2 * 64 * KROW;     // [64][68], xor-swizzled 4-row chunks
    u64* Qs2 = (u64*)Qs;
    u64* Ks2 = (u64*)Ks;

    const int qt = 15 - blockIdx.y;      // LPT: heaviest tiles first
    const int b  = blockIdx.x;
    const int t  = threadIdx.x;
    const int rg = t >> 4, cg = t & 15;
    const int qrow0 = qt * 64;
    const float* Qg = g_q    + (size_t)b * TT * HID;
    const float* Og = g_outs + (size_t)b * TT * HID;

    {
        const u64 sc2 = splat2(0.08838834764831845f);
        const u64* Qg2 = (const u64*)Qg;
        #pragma unroll
        for (int j = 0; j < 16; j++) {
            int idx2 = t + 256 * j;
            int r = idx2 >> 6, h2 = idx2 & 63;
            u64 v = Qg2[(size_t)(qrow0 + r) * (HID/2) + h2];
            Qs2[r * KROW2 + h2] = mul2(v, sc2);
        }
    }

    float m[4], lsum[4];
    u64 O2[4][4];
    #pragma unroll
    for (int rr = 0; rr < 4; rr++) {
        m[rr] = -1e30f; lsum[rr] = 0.f;
        #pragma unroll
        for (int j = 0; j < 4; j++) O2[rr][j] = 0ull;
    }

    const int nkt = qt + 1;
    for (int kt = 0; kt < nkt; kt++) {
        __syncthreads();
        {
            const u64* Og2 = (const u64*)Og;
            #pragma unroll
            for (int j = 0; j < 16; j++) {
                int idx2 = t + 256 * j;
                int s = idx2 >> 6, h2 = idx2 & 63;
                Ks2[s * KROW2 + h2] = Og2[(size_t)(kt * 64 + s) * (HID/2) + h2];
            }
        }
        __syncthreads();

        u64 a2[4][4];
        #pragma unroll
        for (int rr = 0; rr < 4; rr++)
            #pragma unroll
            for (int cc = 0; cc < 4; cc++) a2[rr][cc] = 0ull;
        {
            const u64* Qp = Qs2 + (rg * 4) * KROW2;
            const u64* Kp = Ks2 + cg * KROW2;
            #pragma unroll 1
            for (int h2 = 0; h2 < 64; h2++) {
                u64 q0 = Qp[h2], q1 = Qp[KROW2 + h2], q2 = Qp[2*KROW2 + h2], q3 = Qp[3*KROW2 + h2];
                u64 k0 = Kp[h2], k1 = Kp[16*KROW2 + h2], k2 = Kp[32*KROW2 + h2], k3 = Kp[48*KROW2 + h2];
                a2[0][0] = fma2(q0, k0, a2[0][0]); a2[0][1] = fma2(q0, k1, a2[0][1]);
                a2[0][2] = fma2(q0, k2, a2[0][2]); a2[0][3] = fma2(q0, k3, a2[0][3]);
                a2[1][0] = fma2(q1, k0, a2[1][0]); a2[1][1] = fma2(q1, k1, a2[1][1]);
                a2[1][2] = fma2(q1, k2, a2[1][2]); a2[1][3] = fma2(q1, k3, a2[1][3]);
                a2[2][0] = fma2(q2, k0, a2[2][0]); a2[2][1] = fma2(q2, k1, a2[2][1]);
                a2[2][2] = fma2(q2, k2, a2[2][2]); a2[2][3] = fma2(q2, k3, a2[2][3]);
                a2[3][0] = fma2(q3, k0, a2[3][0]); a2[3][1] = fma2(q3, k1, a2[3][1]);
                a2[3][2] = fma2(q3, k2, a2[3][2]); a2[3][3] = fma2(q3, k3, a2[3][3]);
            }
        }

        float S[4][4];
        #pragma unroll
        for (int rr = 0; rr < 4; rr++)
            #pragma unroll
            for (int cc = 0; cc < 4; cc++) S[rr][cc] = hadd2(a2[rr][cc]);

        if (kt == qt) {
            #pragma unroll
            for (int rr = 0; rr < 4; rr++) {
                int rl = rg * 4 + rr;
                #pragma unroll
                for (int cc = 0; cc < 4; cc++)
                    if (16 * cc + cg > rl) S[rr][cc] = -1e30f;
            }
        }

        #pragma unroll
        for (int rr = 0; rr < 4; rr++) {
            float pm = fmaxf(fmaxf(S[rr][0], S[rr][1]), fmaxf(S[rr][2], S[rr][3]));
            pm = fmaxf(pm, __shfl_xor_sync(0xffffffffu, pm, 1));
            pm = fmaxf(pm, __shfl_xor_sync(0xffffffffu, pm, 2));
            pm = fmaxf(pm, __shfl_xor_sync(0xffffffffu, pm, 4));
            pm = fmaxf(pm, __shfl_xor_sync(0xffffffffu, pm, 8));
            float mn = fmaxf(m[rr], pm);
            float alpha = __expf(m[rr] - mn);
            float rs = 0.f;
            #pragma unroll
            for (int cc = 0; cc < 4; cc++) {
                S[rr][cc] = __expf(S[rr][cc] - mn);
                rs += S[rr][cc];
            }
            rs += __shfl_xor_sync(0xffffffffu, rs, 1);
            rs += __shfl_xor_sync(0xffffffffu, rs, 2);
            rs += __shfl_xor_sync(0xffffffffu, rs, 4);
            rs += __shfl_xor_sync(0xffffffffu, rs, 8);
            lsum[rr] = lsum[rr] * alpha + rs;
            m[rr] = mn;
            u64 as = splat2(alpha);
            #pragma unroll
            for (int j = 0; j < 4; j++) O2[rr][j] = mul2(O2[rr][j], as);
        }

        {
            int ch = (rg ^ cg) * 4;
            #pragma unroll
            for (int cc = 0; cc < 4; cc++) {
                int s = 16 * cc + cg;
                float* p = St + s * 68 + ch;
                #pragma unroll
                for (int rr = 0; rr < 4; rr++) p[rr] = S[rr][cc];
            }
        }
        __syncthreads();

        #pragma unroll 1
        for (int s = 0; s < 64; s++) {
            float4 p4 = *(const float4*)(St + s * 68 + ((rg ^ (s & 15)) * 4));
            const u64* Vp = Ks2 + s * KROW2 + cg;
            u64 v0 = Vp[0], v1 = Vp[16], v2 = Vp[32], v3 = Vp[48];
            u64 p0 = splat2(p4.x), p1 = splat2(p4.y), p2 = splat2(p4.z), p3 = splat2(p4.w);
            O2[0][0] = fma2(p0, v0, O2[0][0]); O2[0][1] = fma2(p0, v1, O2[0][1]);
            O2[0][2] = fma2(p0, v2, O2[0][2]); O2[0][3] = fma2(p0, v3, O2[0][3]);
            O2[1][0] = fma2(p1, v0, O2[1][0]); O2[1][1] = fma2(p1, v1, O2[1][1]);
            O2[1][2] = fma2(p1, v2, O2[1][2]); O2[1][3] = fma2(p1, v3, O2[1][3]);
            O2[2][0] = fma2(p2, v0, O2[2][0]); O2[2][1] = fma2(p2, v1, O2[2][1]);
            O2[2][2] = fma2(p2, v2, O2[2][2]); O2[2][3] = fma2(p2, v3, O2[2][3]);
            O2[3][0] = fma2(p3, v0, O2[3][0]); O2[3][1] = fma2(p3, v1, O2[3][1]);
            O2[3][2] = fma2(p3, v2, O2[3][2]); O2[3][3] = fma2(p3, v3, O2[3][3]);
        }
    }

    float* Cg = g_ctx + (size_t)b * TT * HID;
    #pragma unroll
    for (int rr = 0; rr < 4; rr++) {
        u64 inv2 = splat2(1.0f / lsum[rr]);
        size_t row = (size_t)qrow0 + rg * 4 + rr;
        #pragma unroll
        for (int j = 0; j < 4; j++) {
            float2 p = unpack2(mul2(O2[rr][j], inv2));
            *(float2*)(Cg + row * HID + 2 * cg + 32 * j) = p;
        }
    }
}

// ---------------------------------------------------------------------------
// FC to vocab
// ---------------------------------------------------------------------------
__global__ __launch_bounds__(256, 1)
void fc_kernel(const float* __restrict__ fc_w, const float* __restrict__ fc_b,
               float* __restrict__ out) {
    extern __shared__ float smf[];
    float* fwt = smf;                 // [k=256][c stride 56]
    float* xst = smf + 256 * 56;      // [k=256][r stride 20]

    const int t = threadIdx.x;
    const int c  = t & 63;
    const int rg = t >> 6;
    const size_t rowbase = (size_t)blockIdx.x * 16;

    for (int idx = t; idx < VOCAB * 256; idx += 256) {
        int cc = idx >> 8, k = idx & 255;
        fwt[k * 56 + cc] = fc_w[idx];
    }
    for (int idx = t; idx < 16 * 256; idx += 256) {
        int r = idx >> 8, k = idx & 255;
        size_t row = rowbase + r;
        float v = (k < HID) ? g_outs[row * HID + k] : g_ctx[row * HID + (k - HID)];
        xst[k * 20 + r] = v;
    }
    __syncthreads();

    if (c < VOCAB) {
        float a0 = 0.f, a1 = 0.f, a2 = 0.f, a3 = 0.f;
        #pragma unroll 4
        for (int k = 0; k < 256; k++) {
            float4 x4 = *(const float4*)(xst + k * 20 + rg * 4);
            float wv = fwt[k * 56 + c];
            a0 = fmaf(x4.x, wv, a0);
            a1 = fmaf(x4.y, wv, a1);
            a2 = fmaf(x4.z, wv, a2);
            a3 = fmaf(x4.w, wv, a3);
        }
        float bb = fc_b[c];
        out[(rowbase + rg * 4 + 0) * VOCAB + c] = a0 + bb;
        out[(rowbase + rg * 4 + 1) * VOCAB + c] = a1 + bb;
        out[(rowbase + rg * 4 + 2) * VOCAB + c] = a2 + bb;
        out[(rowbase + rg * 4 + 3) * VOCAB + c] = a3 + bb;
    }
}

// ---------------------------------------------------------------------------
extern "C" void kernel_launch(void* const* d_in, const int* in_sizes, int n_in,
                              void* d_out, int out_size) {
    const int*   x      = (const int*)  d_in[0];
    const float* emb    = (const float*)d_in[1];
    const float* w_ih0  = (const float*)d_in[2];
    const float* b_ih0  = (const float*)d_in[3];
    const float* w_hh0  = (const float*)d_in[4];
    const float* b_hh0  = (const float*)d_in[5];
    const float* w_ih1  = (const float*)d_in[6];
    const float* b_ih1  = (const float*)d_in[7];
    const float* w_hh1  = (const float*)d_in[8];
    const float* b_hh1  = (const float*)d_in[9];
    const float* attn_w = (const float*)d_in[10];
    const float* attn_b = (const float*)d_in[11];
    const float* fc_w   = (const float*)d_in[12];
    const float* fc_b   = (const float*)d_in[13];
    float* out = (float*)d_out;

    const int QSMEM = (128 * 132 + 128 * 68) * 4;      // 102400
    const int ASMEM = (2 * 64 * KROW + 64 * 68) * 4;   // 83968
    const int FSMEM = (256 * 56 + 256 * 20) * 4;       // 77824
    cudaFuncSetAttribute((const void*)q_kernel,
                         cudaFuncAttributeMaxDynamicSharedMemorySize, QSMEM);
    cudaFuncSetAttribute((const void*)attn_kernel,
                         cudaFuncAttributeMaxDynamicSharedMemorySize, ASMEM);
    cudaFuncSetAttribute((const void*)fc_kernel,
                         cudaFuncAttributeMaxDynamicSharedMemorySize, FSMEM);

    reset_kernel<<<1, 128>>>();                        // graph-replay safe flags
    tab0_kernel<<<VOCAB, HID>>>(emb, w_ih0, b_ih0, b_hh0);
    rnn_kernel<<<2 * BB, 256>>>(x, w_hh0, w_ih1, b_ih1, w_hh1, b_hh1);
    q_kernel<<<(BB * TT) / 64, 256, QSMEM>>>(attn_w, attn_b);
    attn_kernel<<<dim3(BB, 16), 256, ASMEM>>>();       // LPT: qt = 15 - blockIdx.y
    fc_kernel<<<(BB * TT) / 16, 256, FSMEM>>>(fc_w, fc_b, out);
}

// round 12
// speedup vs baseline: 1.4671x; 1.4671x over previous
#include <cuda_runtime.h>
#include <math.h>
#include <stddef.h>

#define BB    64
#define TT    1024
#define VOCAB 55
#define EMBED 64
#define HID   128

typedef unsigned long long u64;

__device__ float g_outs[BB * TT * HID];
__device__ float g_q   [BB * TT * HID];
__device__ float g_ctx [BB * TT * HID];
__device__ float g_tab0[VOCAB * HID];

// Packed f32x2 helpers
__device__ __forceinline__ u64 fma2(u64 a, u64 b, u64 c) {
    u64 d; asm("fma.rn.f32x2 %0, %1, %2, %3;" : "=l"(d) : "l"(a), "l"(b), "l"(c));
    return d;
}
__device__ __forceinline__ u64 add2(u64 a, u64 b) {
    u64 d; asm("add.rn.f32x2 %0, %1, %2;" : "=l"(d) : "l"(a), "l"(b));
    return d;
}
__device__ __forceinline__ u64 mul2(u64 a, u64 b) {
    u64 d; asm("mul.rn.f32x2 %0, %1, %2;" : "=l"(d) : "l"(a), "l"(b));
    return d;
}
__device__ __forceinline__ u64 splat2(float v) {
    u64 r; asm("mov.b64 %0, {%1, %1};" : "=l"(r) : "f"(v));
    return r;
}
__device__ __forceinline__ float2 unpack2(u64 v) {
    float lo, hi; asm("mov.b64 {%0, %1}, %2;" : "=f"(lo), "=f"(hi) : "l"(v));
    return make_float2(lo, hi);
}
__device__ __forceinline__ float hadd2(u64 v) {
    float2 p = unpack2(v); return p.x + p.y;
}
__device__ __forceinline__ float tanh_fast(float x) {
    float e = __expf(2.0f * x);
    return 1.0f - __fdividef(2.0f, e + 1.0f);
}

#define BAR_SYNC(id, cnt)   asm volatile("bar.sync %0, %1;"   :: "r"(id), "r"(cnt) : "memory")
#define BAR_ARRIVE(id, cnt) asm volatile("bar.arrive %0, %1;" :: "r"(id), "r"(cnt) : "memory")

// ---------------------------------------------------------------------------
__global__ void tab0_kernel(const float* __restrict__ emb,
                            const float* __restrict__ w_ih0,
                            const float* __restrict__ b_ih0,
                            const float* __restrict__ b_hh0) {
    __shared__ float es[EMBED];
    int v = blockIdx.x;
    int i = threadIdx.x;
    if (i < EMBED) es[i] = emb[v * EMBED + i];
    __syncthreads();
    float acc = b_ih0[i] + b_hh0[i];
    #pragma unroll
    for (int e = 0; e < EMBED; e++)
        acc += es[e] * w_ih0[i * EMBED + e];
    g_tab0[v * HID + i] = acc;
}

// ---------------------------------------------------------------------------
// Warp-specialized RNN scan (round-10 winner, reverted): 4-slot h0 pipeline.
//   Group A (thr 0..127):  layer0 producer, runs ahead <=4 steps.
//   Group B (thr 128..383): layer1 consumer (q=0: ih1 dot h0; q=1: hh1 dot h1).
// Barriers: data A->B id 2+(st&3) cnt 384; credit B->A id 6+(st&3) cnt 384;
// A-internal id 1 cnt 128 only for st<4; no B-internal barrier.
// ---------------------------------------------------------------------------
__global__ __launch_bounds__(384, 1)
void rnn_kernel(const int*   __restrict__ x,
                const float* __restrict__ w_hh0,
                const float* __restrict__ w_ih1,
                const float* __restrict__ b_ih1,
                const float* __restrict__ w_hh1,
                const float* __restrict__ b_hh1) {
    __shared__ float tab0s[VOCAB * HID];
    __shared__ int   xs[TT];
    __shared__ __align__(16) float h0b[4][HID];
    __shared__ __align__(16) float h1b[2][HID];

    const int b = blockIdx.x;
    const int t = threadIdx.x;

    for (int idx = t; idx < VOCAB * HID; idx += 384) tab0s[idx] = g_tab0[idx];
    for (int idx = t; idx < TT;          idx += 384) xs[idx]    = x[b * TT + idx];
    if (t < HID) {
        h0b[0][t] = 0.f; h0b[1][t] = 0.f; h0b[2][t] = 0.f; h0b[3][t] = 0.f;
        h1b[0][t] = 0.f; h1b[1][t] = 0.f;
    }

    const int  bidx = t - 128;
    const int  bi   = bidx >> 1;        // valid for t >= 128
    const int  bq   = bidx & 1;
    const float* wsrc;
    if (t < 128)      wsrc = w_hh0 + t * HID;
    else if (bq == 0) wsrc = w_ih1 + bi * HID;
    else              wsrc = w_hh1 + bi * HID;

    u64 wreg[64];
    {
        const ulonglong2* wp = (const ulonglong2*)wsrc;
        #pragma unroll
        for (int m = 0; m < 32; m++) { ulonglong2 v = wp[m]; wreg[2*m] = v.x; wreg[2*m+1] = v.y; }
    }

    __syncthreads();

    float* outp = g_outs + (size_t)b * TT * HID;

    if (t < 128) {
        // ---------------- Group A: layer0 producer ----------------
        #pragma unroll 1
        for (int st = 0; st < TT; st++) {
            const int sl = st & 3, prev = (st - 1) & 3;
            if (st >= 4) BAR_SYNC(6 + sl, 384);          // B consumed slot sl @ st-4
            const float tb = tab0s[xs[st] * HID + t];
            const ulonglong2* hp = (const ulonglong2*)(&h0b[prev][0]);
            u64 a0 = 0, a1 = 0, a2 = 0, a3 = 0;
            #pragma unroll
            for (int m = 0; m < 16; m++) {
                ulonglong2 va = hp[2*m], vb = hp[2*m+1];
                a0 = fma2(va.x, wreg[4*m],     a0);
                a1 = fma2(va.y, wreg[4*m + 1], a1);
                a2 = fma2(vb.x, wreg[4*m + 2], a2);
                a3 = fma2(vb.y, wreg[4*m + 3], a3);
            }
            float acc = hadd2(add2(add2(a0, a1), add2(a2, a3)));
            float h0n = tanh_fast(acc + tb);
            h0b[sl][t] = h0n;
            BAR_ARRIVE(2 + sl, 384);                     // h0(st) ready for B
            if (st < 4) BAR_SYNC(1, 128);                // early-step A ordering
        }
    } else {
        // ---------------- Group B: layer1 consumer ----------------
        const float c1 = b_ih1[bi] + b_hh1[bi];
        #pragma unroll 1
        for (int st = 0; st < TT; st++) {
            const int sl = st & 3, p1 = st & 1;
            BAR_SYNC(2 + sl, 384);                       // wait h0(st)
            const ulonglong2* sp = (const ulonglong2*)(bq ? &h1b[p1 ^ 1][0] : &h0b[sl][0]);
            u64 a0 = 0, a1 = 0, a2 = 0, a3 = 0;
            #pragma unroll
            for (int m = 0; m < 16; m++) {
                ulonglong2 va = sp[2*m], vb = sp[2*m+1];
                a0 = fma2(va.x, wreg[4*m],     a0);
                a1 = fma2(va.y, wreg[4*m + 1], a1);
                a2 = fma2(vb.x, wreg[4*m + 2], a2);
                a3 = fma2(vb.y, wreg[4*m + 3], a3);
            }
            float acc = hadd2(add2(add2(a0, a1), add2(a2, a3)));
            acc += __shfl_xor_sync(0xffffffffu, acc, 1);
            BAR_ARRIVE(6 + sl, 384);                     // credit: slot sl consumed
            float h1n = tanh_fast(acc + c1);
            if (!bq) {
                h1b[p1][bi] = h1n;
                outp[st * HID + bi] = h1n;
            }
        }
    }
}

// ---------------------------------------------------------------------------
// Q projection: 2 row-tiles (2x64 rows) per block, wt loaded ONCE per block.
// ---------------------------------------------------------------------------
__global__ __launch_bounds__(256, 1)
void q_kernel(const float* __restrict__ attn_w, const float* __restrict__ attn_b) {
    extern __shared__ float smq[];
    float* wt  = smq;                 // [k=128][i stride 132]
    float* ost = smq + 128 * 132;     // [k=128][r stride 68]
    __shared__ float bs[HID];

    const int t = threadIdx.x;
    const int rg = t >> 4, cg = t & 15;

    for (int idx = t; idx < HID * HID; idx += 256) {
        int i = idx >> 7, k = idx & 127;
        wt[k * 132 + i] = attn_w[idx];
    }
    if (t < HID) bs[t] = attn_b[t];

    #pragma unroll 1
    for (int half = 0; half < 2; half++) {
        const size_t rowbase = (size_t)blockIdx.x * 128 + half * 64;
        __syncthreads();   // wt ready (half 0) / prior ost reads done (half 1)
        for (int idx = t; idx < 64 * HID; idx += 256) {
            int r = idx >> 7, k = idx & 127;
            ost[k * 68 + r] = g_outs[(rowbase + r) * HID + k];
        }
        __syncthreads();

        u64 acc[4][4];
        #pragma unroll
        for (int rr = 0; rr < 4; rr++)
            #pragma unroll
            for (int c = 0; c < 4; c++) acc[rr][c] = 0ull;

        #pragma unroll 2
        for (int k = 0; k < HID; k++) {
            float4 q4 = *(const float4*)(ost + k * 68 + rg * 4);
            ulonglong2 w0 = *(const ulonglong2*)(wt + k * 132 + cg * 8);
            ulonglong2 w1 = *(const ulonglong2*)(wt + k * 132 + cg * 8 + 4);
            float qv[4] = {q4.x, q4.y, q4.z, q4.w};
            #pragma unroll
            for (int rr = 0; rr < 4; rr++) {
                u64 qs = splat2(qv[rr]);
                acc[rr][0] = fma2(qs, w0.x, acc[rr][0]);
                acc[rr][1] = fma2(qs, w0.y, acc[rr][1]);
                acc[rr][2] = fma2(qs, w1.x, acc[rr][2]);
                acc[rr][3] = fma2(qs, w1.y, acc[rr][3]);
            }
        }

        #pragma unroll
        for (int rr = 0; rr < 4; rr++) {
            size_t row = rowbase + rg * 4 + rr;
            float o[8];
            #pragma unroll
            for (int c = 0; c < 4; c++) {
                float2 p = unpack2(acc[rr][c]);
                o[2*c]   = p.x + bs[cg * 8 + 2*c];
                o[2*c+1] = p.y + bs[cg * 8 + 2*c + 1];
            }
            *(float4*)(g_q + row * HID + cg * 8)     = make_float4(o[0], o[1], o[2], o[3]);
            *(float4*)(g_q + row * HID + cg * 8 + 4) = make_float4(o[4], o[5], o[6], o[7]);
        }
    }
}

// ---------------------------------------------------------------------------
// Flash attention, 2 CTAs/SM, LPT ordering (round-10 winner, unchanged).
// ---------------------------------------------------------------------------
#define KROW  130
#define KROW2 65

__global__ __launch_bounds__(256, 2)
void attn_kernel() {
    extern __shared__ float sma[];
    float* Qs = sma;                     // [64][130]
    float* Ks = sma + 64 * KROW;         // [64][130]
    float* St = sma + 2 * 64 * KROW;     // [64][68], xor-swizzled 4-row chunks
    u64* Qs2 = (u64*)Qs;
    u64* Ks2 = (u64*)Ks;

    const int qt = 15 - blockIdx.y;      // LPT: heaviest tiles first
    const int b  = blockIdx.x;
    const int t  = threadIdx.x;
    const int rg = t >> 4, cg = t & 15;
    const int qrow0 = qt * 64;
    const float* Qg = g_q    + (size_t)b * TT * HID;
    const float* Og = g_outs + (size_t)b * TT * HID;

    {
        const u64 sc2 = splat2(0.08838834764831845f);
        const u64* Qg2 = (const u64*)Qg;
        #pragma unroll
        for (int j = 0; j < 16; j++) {
            int idx2 = t + 256 * j;
            int r = idx2 >> 6, h2 = idx2 & 63;
            u64 v = Qg2[(size_t)(qrow0 + r) * (HID/2) + h2];
            Qs2[r * KROW2 + h2] = mul2(v, sc2);
        }
    }

    float m[4], lsum[4];
    u64 O2[4][4];
    #pragma unroll
    for (int rr = 0; rr < 4; rr++) {
        m[rr] = -1e30f; lsum[rr] = 0.f;
        #pragma unroll
        for (int j = 0; j < 4; j++) O2[rr][j] = 0ull;
    }

    const int nkt = qt + 1;
    for (int kt = 0; kt < nkt; kt++) {
        __syncthreads();
        {
            const u64* Og2 = (const u64*)Og;
            #pragma unroll
            for (int j = 0; j < 16; j++) {
                int idx2 = t + 256 * j;
                int s = idx2 >> 6, h2 = idx2 & 63;
                Ks2[s * KROW2 + h2] = Og2[(size_t)(kt * 64 + s) * (HID/2) + h2];
            }
        }
        __syncthreads();

        u64 a2[4][4];
        #pragma unroll
        for (int rr = 0; rr < 4; rr++)
            #pragma unroll
            for (int cc = 0; cc < 4; cc++) a2[rr][cc] = 0ull;
        {
            const u64* Qp = Qs2 + (rg * 4) * KROW2;
            const u64* Kp = Ks2 + cg * KROW2;
            #pragma unroll 1
            for (int h2 = 0; h2 < 64; h2++) {
                u64 q0 = Qp[h2], q1 = Qp[KROW2 + h2], q2 = Qp[2*KROW2 + h2], q3 = Qp[3*KROW2 + h2];
                u64 k0 = Kp[h2], k1 = Kp[16*KROW2 + h2], k2 = Kp[32*KROW2 + h2], k3 = Kp[48*KROW2 + h2];
                a2[0][0] = fma2(q0, k0, a2[0][0]); a2[0][1] = fma2(q0, k1, a2[0][1]);
                a2[0][2] = fma2(q0, k2, a2[0][2]); a2[0][3] = fma2(q0, k3, a2[0][3]);
                a2[1][0] = fma2(q1, k0, a2[1][0]); a2[1][1] = fma2(q1, k1, a2[1][1]);
                a2[1][2] = fma2(q1, k2, a2[1][2]); a2[1][3] = fma2(q1, k3, a2[1][3]);
                a2[2][0] = fma2(q2, k0, a2[2][0]); a2[2][1] = fma2(q2, k1, a2[2][1]);
                a2[2][2] = fma2(q2, k2, a2[2][2]); a2[2][3] = fma2(q2, k3, a2[2][3]);
                a2[3][0] = fma2(q3, k0, a2[3][0]); a2[3][1] = fma2(q3, k1, a2[3][1]);
                a2[3][2] = fma2(q3, k2, a2[3][2]); a2[3][3] = fma2(q3, k3, a2[3][3]);
            }
        }

        float S[4][4];
        #pragma unroll
        for (int rr = 0; rr < 4; rr++)
            #pragma unroll
            for (int cc = 0; cc < 4; cc++) S[rr][cc] = hadd2(a2[rr][cc]);

        if (kt == qt) {
            #pragma unroll
            for (int rr = 0; rr < 4; rr++) {
                int rl = rg * 4 + rr;
                #pragma unroll
                for (int cc = 0; cc < 4; cc++)
                    if (16 * cc + cg > rl) S[rr][cc] = -1e30f;
            }
        }

        #pragma unroll
        for (int rr = 0; rr < 4; rr++) {
            float pm = fmaxf(fmaxf(S[rr][0], S[rr][1]), fmaxf(S[rr][2], S[rr][3]));
            pm = fmaxf(pm, __shfl_xor_sync(0xffffffffu, pm, 1));
            pm = fmaxf(pm, __shfl_xor_sync(0xffffffffu, pm, 2));
            pm = fmaxf(pm, __shfl_xor_sync(0xffffffffu, pm, 4));
            pm = fmaxf(pm, __shfl_xor_sync(0xffffffffu, pm, 8));
            float mn = fmaxf(m[rr], pm);
            float alpha = __expf(m[rr] - mn);
            float rs = 0.f;
            #pragma unroll
            for (int cc = 0; cc < 4; cc++) {
                S[rr][cc] = __expf(S[rr][cc] - mn);
                rs += S[rr][cc];
            }
            rs += __shfl_xor_sync(0xffffffffu, rs, 1);
            rs += __shfl_xor_sync(0xffffffffu, rs, 2);
            rs += __shfl_xor_sync(0xffffffffu, rs, 4);
            rs += __shfl_xor_sync(0xffffffffu, rs, 8);
            lsum[rr] = lsum[rr] * alpha + rs;
            m[rr] = mn;
            u64 as = splat2(alpha);
            #pragma unroll
            for (int j = 0; j < 4; j++) O2[rr][j] = mul2(O2[rr][j], as);
        }

        {
            int ch = (rg ^ cg) * 4;
            #pragma unroll
            for (int cc = 0; cc < 4; cc++) {
                int s = 16 * cc + cg;
                float* p = St + s * 68 + ch;
                #pragma unroll
                for (int rr = 0; rr < 4; rr++) p[rr] = S[rr][cc];
            }
        }
        __syncthreads();

        #pragma unroll 1
        for (int s = 0; s < 64; s++) {
            float4 p4 = *(const float4*)(St + s * 68 + ((rg ^ (s & 15)) * 4));
            const u64* Vp = Ks2 + s * KROW2 + cg;
            u64 v0 = Vp[0], v1 = Vp[16], v2 = Vp[32], v3 = Vp[48];
            u64 p0 = splat2(p4.x), p1 = splat2(p4.y), p2 = splat2(p4.z), p3 = splat2(p4.w);
            O2[0][0] = fma2(p0, v0, O2[0][0]); O2[0][1] = fma2(p0, v1, O2[0][1]);
            O2[0][2] = fma2(p0, v2, O2[0][2]); O2[0][3] = fma2(p0, v3, O2[0][3]);
            O2[1][0] = fma2(p1, v0, O2[1][0]); O2[1][1] = fma2(p1, v1, O2[1][1]);
            O2[1][2] = fma2(p1, v2, O2[1][2]); O2[1][3] = fma2(p1, v3, O2[1][3]);
            O2[2][0] = fma2(p2, v0, O2[2][0]); O2[2][1] = fma2(p2, v1, O2[2][1]);
            O2[2][2] = fma2(p2, v2, O2[2][2]); O2[2][3] = fma2(p2, v3, O2[2][3]);
            O2[3][0] = fma2(p3, v0, O2[3][0]); O2[3][1] = fma2(p3, v1, O2[3][1]);
            O2[3][2] = fma2(p3, v2, O2[3][2]); O2[3][3] = fma2(p3, v3, O2[3][3]);
        }
    }

    float* Cg = g_ctx + (size_t)b * TT * HID;
    #pragma unroll
    for (int rr = 0; rr < 4; rr++) {
        u64 inv2 = splat2(1.0f / lsum[rr]);
        size_t row = (size_t)qrow0 + rg * 4 + rr;
        #pragma unroll
        for (int j = 0; j < 4; j++) {
            float2 p = unpack2(mul2(O2[rr][j], inv2));
            *(float2*)(Cg + row * HID + 2 * cg + 32 * j) = p;
        }
    }
}

// ---------------------------------------------------------------------------
// FC to vocab: 4 row-tiles (4x16 rows) per block, fwt loaded ONCE per block.
// ---------------------------------------------------------------------------
__global__ __launch_bounds__(256, 1)
void fc_kernel(const float* __restrict__ fc_w, const float* __restrict__ fc_b,
               float* __restrict__ out) {
    extern __shared__ float smf[];
    float* fwt = smf;                 // [k=256][c stride 56]
    float* xst = smf + 256 * 56;      // [k=256][r stride 20]

    const int t = threadIdx.x;
    const int c  = t & 63;
    const int rg = t >> 6;

    for (int idx = t; idx < VOCAB * 256; idx += 256) {
        int cc = idx >> 8, k = idx & 255;
        fwt[k * 56 + cc] = fc_w[idx];
    }
    const float bb = (c < VOCAB) ? fc_b[c] : 0.f;

    #pragma unroll 1
    for (int part = 0; part < 4; part++) {
        const size_t rowbase = (size_t)blockIdx.x * 64 + part * 16;
        __syncthreads();   // fwt ready (part 0) / prior xst reads done
        for (int idx = t; idx < 16 * 256; idx += 256) {
            int r = idx >> 8, k = idx & 255;
            size_t row = rowbase + r;
            float v = (k < HID) ? g_outs[row * HID + k] : g_ctx[row * HID + (k - HID)];
            xst[k * 20 + r] = v;
        }
        __syncthreads();

        if (c < VOCAB) {
            float a0 = 0.f, a1 = 0.f, a2 = 0.f, a3 = 0.f;
            #pragma unroll 4
            for (int k = 0; k < 256; k++) {
                float4 x4 = *(const float4*)(xst + k * 20 + rg * 4);
                float wv = fwt[k * 56 + c];
                a0 = fmaf(x4.x, wv, a0);
                a1 = fmaf(x4.y, wv, a1);
                a2 = fmaf(x4.z, wv, a2);
                a3 = fmaf(x4.w, wv, a3);
            }
            out[(rowbase + rg * 4 + 0) * VOCAB + c] = a0 + bb;
            out[(rowbase + rg * 4 + 1) * VOCAB + c] = a1 + bb;
            out[(rowbase + rg * 4 + 2) * VOCAB + c] = a2 + bb;
            out[(rowbase + rg * 4 + 3) * VOCAB + c] = a3 + bb;
        }
    }
}

// ---------------------------------------------------------------------------
extern "C" void kernel_launch(void* const* d_in, const int* in_sizes, int n_in,
                              void* d_out, int out_size) {
    const int*   x      = (const int*)  d_in[0];
    const float* emb    = (const float*)d_in[1];
    const float* w_ih0  = (const float*)d_in[2];
    const float* b_ih0  = (const float*)d_in[3];
    const float* w_hh0  = (const float*)d_in[4];
    const float* b_hh0  = (const float*)d_in[5];
    const float* w_ih1  = (const float*)d_in[6];
    const float* b_ih1  = (const float*)d_in[7];
    const float* w_hh1  = (const float*)d_in[8];
    const float* b_hh1  = (const float*)d_in[9];
    const float* attn_w = (const float*)d_in[10];
    const float* attn_b = (const float*)d_in[11];
    const float* fc_w   = (const float*)d_in[12];
    const float* fc_b   = (const float*)d_in[13];
    float* out = (float*)d_out;

    const int QSMEM = (128 * 132 + 128 * 68) * 4;      // 102400
    const int ASMEM = (2 * 64 * KROW + 64 * 68) * 4;   // 83968
    const int FSMEM = (256 * 56 + 256 * 20) * 4;       // 77824
    cudaFuncSetAttribute((const void*)q_kernel,
                         cudaFuncAttributeMaxDynamicSharedMemorySize, QSMEM);
    cudaFuncSetAttribute((const void*)attn_kernel,
                         cudaFuncAttributeMaxDynamicSharedMemorySize, ASMEM);
    cudaFuncSetAttribute((const void*)fc_kernel,
                         cudaFuncAttributeMaxDynamicSharedMemorySize, FSMEM);

    tab0_kernel<<<VOCAB, HID>>>(emb, w_ih0, b_ih0, b_hh0);
    rnn_kernel<<<BB, 384>>>(x, w_hh0, w_ih1, b_ih1, w_hh1, b_hh1);
    q_kernel<<<(BB * TT) / 128, 256, QSMEM>>>(attn_w, attn_b);
    attn_kernel<<<dim3(BB, 16), 256, ASMEM>>>();       // LPT: qt = 15 - blockIdx.y
    fc_kernel<<<(BB * TT) / 64, 256, FSMEM>>>(fc_w, fc_b, out);
}

// round 14
// speedup vs baseline: 1.7880x; 1.2187x over previous
#include <cuda_runtime.h>
#include <math.h>
#include <stddef.h>

#define BB    64
#define TT    1024
#define VOCAB 55
#define EMBED 64
#define HID   128

typedef unsigned long long u64;

__device__ float g_outs[BB * TT * HID];
__device__ float g_q   [BB * TT * HID];
__device__ float g_ctx [BB * TT * HID];
__device__ float g_tab0[VOCAB * HID];

// Packed f32x2 helpers
__device__ __forceinline__ u64 fma2(u64 a, u64 b, u64 c) {
    u64 d; asm("fma.rn.f32x2 %0, %1, %2, %3;" : "=l"(d) : "l"(a), "l"(b), "l"(c));
    return d;
}
__device__ __forceinline__ u64 add2(u64 a, u64 b) {
    u64 d; asm("add.rn.f32x2 %0, %1, %2;" : "=l"(d) : "l"(a), "l"(b));
    return d;
}
__device__ __forceinline__ u64 mul2(u64 a, u64 b) {
    u64 d; asm("mul.rn.f32x2 %0, %1, %2;" : "=l"(d) : "l"(a), "l"(b));
    return d;
}
__device__ __forceinline__ u64 splat2(float v) {
    u64 r; asm("mov.b64 %0, {%1, %1};" : "=l"(r) : "f"(v));
    return r;
}
__device__ __forceinline__ float2 unpack2(u64 v) {
    float lo, hi; asm("mov.b64 {%0, %1}, %2;" : "=f"(lo), "=f"(hi) : "l"(v));
    return make_float2(lo, hi);
}
__device__ __forceinline__ float hadd2(u64 v) {
    float2 p = unpack2(v); return p.x + p.y;
}
__device__ __forceinline__ float tanh_fast(float x) {
    float e = __expf(2.0f * x);
    return 1.0f - __fdividef(2.0f, e + 1.0f);
}

#define BAR_SYNC(id, cnt)   asm volatile("bar.sync %0, %1;"   :: "r"(id), "r"(cnt) : "memory")
#define BAR_ARRIVE(id, cnt) asm volatile("bar.arrive %0, %1;" :: "r"(id), "r"(cnt) : "memory")

// ---------------------------------------------------------------------------
__global__ void dummy_kernel() {}   // launch-index shim so ncu captures rnn

// ---------------------------------------------------------------------------
__global__ void tab0_kernel(const float* __restrict__ emb,
                            const float* __restrict__ w_ih0,
                            const float* __restrict__ b_ih0,
                            const float* __restrict__ b_hh0) {
    __shared__ float es[EMBED];
    int v = blockIdx.x;
    int i = threadIdx.x;
    if (i < EMBED) es[i] = emb[v * EMBED + i];
    __syncthreads();
    float acc = b_ih0[i] + b_hh0[i];
    #pragma unroll
    for (int e = 0; e < EMBED; e++)
        acc += es[e] * w_ih0[i * EMBED + e];
    g_tab0[v * HID + i] = acc;
}

// ---------------------------------------------------------------------------
// 3-group warp-specialized RNN scan. 384 thr/block, one block per batch.
//   A (0..127):   layer0: h0(t) = tanh(tab0[x_t] + W_hh0 h0(t-1)); runs <=4 ahead.
//   C (128..255): feed-forward uv(t) = W_ih1 h0(t) + b_ih1 + b_hh1; ~1 ahead of D.
//   D (256..383): serial recurrence h1(t) = tanh(W_hh1 h1(t-1) + uv(t)).
//                 ONE thread per output, full w_hh1 row in regs, no shuffle.
// Barriers (count = arrivers + syncers, verified):
//   dataAC 2+(st&3) cnt 256 | credCA 6+(st&3) cnt 256
//   dataCD 10+(st&1) cnt 256 | credDC 12+(st&1) cnt 256 | A-early id 1 cnt 128.
// ---------------------------------------------------------------------------
__global__ __launch_bounds__(384, 1)
void rnn_kernel(const int*   __restrict__ x,
                const float* __restrict__ w_hh0,
                const float* __restrict__ w_ih1,
                const float* __restrict__ b_ih1,
                const float* __restrict__ w_hh1,
                const float* __restrict__ b_hh1) {
    __shared__ float tab0s[VOCAB * HID];
    __shared__ int   xs[TT];
    __shared__ __align__(16) float h0b[4][HID];
    __shared__ __align__(16) float uvb[2][HID];
    __shared__ __align__(16) float h1b[2][HID];

    const int b = blockIdx.x;
    const int t = threadIdx.x;

    for (int idx = t; idx < VOCAB * HID; idx += 384) tab0s[idx] = g_tab0[idx];
    for (int idx = t; idx < TT;          idx += 384) xs[idx]    = x[b * TT + idx];
    if (t < HID) {
        h0b[0][t] = 0.f; h0b[1][t] = 0.f; h0b[2][t] = 0.f; h0b[3][t] = 0.f;
        h1b[0][t] = 0.f; h1b[1][t] = 0.f;
    }

    float* outp = g_outs + (size_t)b * TT * HID;

    if (t < 128) {
        // ================= Group A: layer0 producer =================
        u64 wreg[64];
        {
            const ulonglong2* wp = (const ulonglong2*)(w_hh0 + t * HID);
            #pragma unroll
            for (int m = 0; m < 32; m++) { ulonglong2 v = wp[m]; wreg[2*m] = v.x; wreg[2*m+1] = v.y; }
        }
        __syncthreads();
        #pragma unroll 1
        for (int st = 0; st < TT; st++) {
            const int sl = st & 3, prev = (st - 1) & 3;
            if (st >= 4) BAR_SYNC(6 + sl, 256);          // C consumed h0b[sl] @ st-4
            const float tb = tab0s[xs[st] * HID + t];
            const ulonglong2* hp = (const ulonglong2*)(&h0b[prev][0]);
            u64 a0 = 0, a1 = 0, a2 = 0, a3 = 0;
            #pragma unroll
            for (int m = 0; m < 16; m++) {
                ulonglong2 va = hp[2*m], vb = hp[2*m+1];
                a0 = fma2(va.x, wreg[4*m],     a0);
                a1 = fma2(va.y, wreg[4*m + 1], a1);
                a2 = fma2(vb.x, wreg[4*m + 2], a2);
                a3 = fma2(vb.y, wreg[4*m + 3], a3);
            }
            float acc = hadd2(add2(add2(a0, a1), add2(a2, a3)));
            float h0n = tanh_fast(acc + tb);
            h0b[sl][t] = h0n;
            BAR_ARRIVE(2 + sl, 256);                     // h0(st) ready for C
            if (st < 4) BAR_SYNC(1, 128);                // early A ordering
        }
    } else if (t < 256) {
        // ================= Group C: uv = W_ih1 h0 + biases (off-chain) ======
        const int i = t - 128;
        u64 wreg[64];
        {
            const ulonglong2* wp = (const ulonglong2*)(w_ih1 + i * HID);
            #pragma unroll
            for (int m = 0; m < 32; m++) { ulonglong2 v = wp[m]; wreg[2*m] = v.x; wreg[2*m+1] = v.y; }
        }
        const float c1 = b_ih1[i] + b_hh1[i];
        __syncthreads();
        #pragma unroll 1
        for (int st = 0; st < TT; st++) {
            const int sl = st & 3, s2 = st & 1;
            BAR_SYNC(2 + sl, 256);                       // wait h0(st)
            if (st >= 2) BAR_SYNC(12 + s2, 256);         // D consumed uv[s2] @ st-2
            const ulonglong2* hp = (const ulonglong2*)(&h0b[sl][0]);
            u64 a0 = 0, a1 = 0, a2 = 0, a3 = 0;
            #pragma unroll
            for (int m = 0; m < 16; m++) {
                ulonglong2 va = hp[2*m], vb = hp[2*m+1];
                a0 = fma2(va.x, wreg[4*m],     a0);
                a1 = fma2(va.y, wreg[4*m + 1], a1);
                a2 = fma2(vb.x, wreg[4*m + 2], a2);
                a3 = fma2(vb.y, wreg[4*m + 3], a3);
            }
            BAR_ARRIVE(6 + sl, 256);                     // credit h0 slot
            float acc = hadd2(add2(add2(a0, a1), add2(a2, a3)));
            uvb[s2][i] = acc + c1;
            BAR_ARRIVE(10 + s2, 256);                    // publish uv(st)
        }
    } else {
        // ================= Group D: serial h1 recurrence ====================
        const int i = t - 256;                           // one output per thread
        u64 wreg[64];                                    // full w_hh1 row i
        {
            const ulonglong2* wp = (const ulonglong2*)(w_hh1 + i * HID);
            #pragma unroll
            for (int m = 0; m < 32; m++) { ulonglong2 v = wp[m]; wreg[2*m] = v.x; wreg[2*m+1] = v.y; }
        }
        __syncthreads();
        #pragma unroll 1
        for (int st = 0; st < TT; st++) {
            const int s2 = st & 1;
            BAR_SYNC(10 + s2, 256);                      // wait uv(st); orders h1b too
            const float uvv = uvb[s2][i];                // ready LDS, overlaps dot
            const ulonglong2* hp = (const ulonglong2*)(&h1b[s2 ^ 1][0]);
            u64 a0 = 0, a1 = 0, a2 = 0, a3 = 0;
            #pragma unroll
            for (int m = 0; m < 16; m++) {
                ulonglong2 va = hp[2*m], vb = hp[2*m+1];
                a0 = fma2(va.x, wreg[4*m],     a0);
                a1 = fma2(va.y, wreg[4*m + 1], a1);
                a2 = fma2(vb.x, wreg[4*m + 2], a2);
                a3 = fma2(vb.y, wreg[4*m + 3], a3);
            }
            float acc = hadd2(add2(add2(a0, a1), add2(a2, a3)));
            float tot = acc + uvv;                       // uv consumed here
            BAR_ARRIVE(12 + s2, 256);                    // credit uv slot
            float h1n = tanh_fast(tot);
            h1b[s2][i] = h1n;
            outp[st * HID + i] = h1n;
            // next step's dataCD sync orders h1b write->read within D
        }
    }
}

// ---------------------------------------------------------------------------
// Q projection: 2 row-tiles (2x64 rows) per block, wt loaded ONCE per block.
// ---------------------------------------------------------------------------
__global__ __launch_bounds__(256, 1)
void q_kernel(const float* __restrict__ attn_w, const float* __restrict__ attn_b) {
    extern __shared__ float smq[];
    float* wt  = smq;                 // [k=128][i stride 132]
    float* ost = smq + 128 * 132;     // [k=128][r stride 68]
    __shared__ float bs[HID];

    const int t = threadIdx.x;
    const int rg = t >> 4, cg = t & 15;

    for (int idx = t; idx < HID * HID; idx += 256) {
        int i = idx >> 7, k = idx & 127;
        wt[k * 132 + i] = attn_w[idx];
    }
    if (t < HID) bs[t] = attn_b[t];

    #pragma unroll 1
    for (int half = 0; half < 2; half++) {
        const size_t rowbase = (size_t)blockIdx.x * 128 + half * 64;
        __syncthreads();
        for (int idx = t; idx < 64 * HID; idx += 256) {
            int r = idx >> 7, k = idx & 127;
            ost[k * 68 + r] = g_outs[(rowbase + r) * HID + k];
        }
        __syncthreads();

        u64 acc[4][4];
        #pragma unroll
        for (int rr = 0; rr < 4; rr++)
            #pragma unroll
            for (int c = 0; c < 4; c++) acc[rr][c] = 0ull;

        #pragma unroll 2
        for (int k = 0; k < HID; k++) {
            float4 q4 = *(const float4*)(ost + k * 68 + rg * 4);
            ulonglong2 w0 = *(const ulonglong2*)(wt + k * 132 + cg * 8);
            ulonglong2 w1 = *(const ulonglong2*)(wt + k * 132 + cg * 8 + 4);
            float qv[4] = {q4.x, q4.y, q4.z, q4.w};
            #pragma unroll
            for (int rr = 0; rr < 4; rr++) {
                u64 qs = splat2(qv[rr]);
                acc[rr][0] = fma2(qs, w0.x, acc[rr][0]);
                acc[rr][1] = fma2(qs, w0.y, acc[rr][1]);
                acc[rr][2] = fma2(qs, w1.x, acc[rr][2]);
                acc[rr][3] = fma2(qs, w1.y, acc[rr][3]);
            }
        }

        #pragma unroll
        for (int rr = 0; rr < 4; rr++) {
            size_t row = rowbase + rg * 4 + rr;
            float o[8];
            #pragma unroll
            for (int c = 0; c < 4; c++) {
                float2 p = unpack2(acc[rr][c]);
                o[2*c]   = p.x + bs[cg * 8 + 2*c];
                o[2*c+1] = p.y + bs[cg * 8 + 2*c + 1];
            }
            *(float4*)(g_q + row * HID + cg * 8)     = make_float4(o[0], o[1], o[2], o[3]);
            *(float4*)(g_q + row * HID + cg * 8 + 4) = make_float4(o[4], o[5], o[6], o[7]);
        }
    }
}

// ---------------------------------------------------------------------------
// Flash attention, 2 CTAs/SM, LPT ordering (unchanged).
// ---------------------------------------------------------------------------
#define KROW  130
#define KROW2 65

__global__ __launch_bounds__(256, 2)
void attn_kernel() {
    extern __shared__ float sma[];
    float* Qs = sma;                     // [64][130]
    float* Ks = sma + 64 * KROW;         // [64][130]
    float* St = sma + 2 * 64 * KROW;     // [64][68], xor-swizzled 4-row chunks
    u64* Qs2 = (u64*)Qs;
    u64* Ks2 = (u64*)Ks;

    const int qt = 15 - blockIdx.y;      // LPT: heaviest tiles first
    const int b  = blockIdx.x;
    const int t  = threadIdx.x;
    const int rg = t >> 4, cg = t & 15;
    const int qrow0 = qt * 64;
    const float* Qg = g_q    + (size_t)b * TT * HID;
    const float* Og = g_outs + (size_t)b * TT * HID;

    {
        const u64 sc2 = splat2(0.08838834764831845f);
        const u64* Qg2 = (const u64*)Qg;
        #pragma unroll
        for (int j = 0; j < 16; j++) {
            int idx2 = t + 256 * j;
            int r = idx2 >> 6, h2 = idx2 & 63;
            u64 v = Qg2[(size_t)(qrow0 + r) * (HID/2) + h2];
            Qs2[r * KROW2 + h2] = mul2(v, sc2);
        }
    }

    float m[4], lsum[4];
    u64 O2[4][4];
    #pragma unroll
    for (int rr = 0; rr < 4; rr++) {
        m[rr] = -1e30f; lsum[rr] = 0.f;
        #pragma unroll
        for (int j = 0; j < 4; j++) O2[rr][j] = 0ull;
    }

    const int nkt = qt + 1;
    for (int kt = 0; kt < nkt; kt++) {
        __syncthreads();
        {
            const u64* Og2 = (const u64*)Og;
            #pragma unroll
            for (int j = 0; j < 16; j++) {
                int idx2 = t + 256 * j;
                int s = idx2 >> 6, h2 = idx2 & 63;
                Ks2[s * KROW2 + h2] = Og2[(size_t)(kt * 64 + s) * (HID/2) + h2];
            }
        }
        __syncthreads();

        u64 a2[4][4];
        #pragma unroll
        for (int rr = 0; rr < 4; rr++)
            #pragma unroll
            for (int cc = 0; cc < 4; cc++) a2[rr][cc] = 0ull;
        {
            const u64* Qp = Qs2 + (rg * 4) * KROW2;
            const u64* Kp = Ks2 + cg * KROW2;
            #pragma unroll 1
            for (int h2 = 0; h2 < 64; h2++) {
                u64 q0 = Qp[h2], q1 = Qp[KROW2 + h2], q2 = Qp[2*KROW2 + h2], q3 = Qp[3*KROW2 + h2];
                u64 k0 = Kp[h2], k1 = Kp[16*KROW2 + h2], k2 = Kp[32*KROW2 + h2], k3 = Kp[48*KROW2 + h2];
                a2[0][0] = fma2(q0, k0, a2[0][0]); a2[0][1] = fma2(q0, k1, a2[0][1]);
                a2[0][2] = fma2(q0, k2, a2[0][2]); a2[0][3] = fma2(q0, k3, a2[0][3]);
                a2[1][0] = fma2(q1, k0, a2[1][0]); a2[1][1] = fma2(q1, k1, a2[1][1]);
                a2[1][2] = fma2(q1, k2, a2[1][2]); a2[1][3] = fma2(q1, k3, a2[1][3]);
                a2[2][0] = fma2(q2, k0, a2[2][0]); a2[2][1] = fma2(q2, k1, a2[2][1]);
                a2[2][2] = fma2(q2, k2, a2[2][2]); a2[2][3] = fma2(q2, k3, a2[2][3]);
                a2[3][0] = fma2(q3, k0, a2[3][0]); a2[3][1] = fma2(q3, k1, a2[3][1]);
                a2[3][2] = fma2(q3, k2, a2[3][2]); a2[3][3] = fma2(q3, k3, a2[3][3]);
            }
        }

        float S[4][4];
        #pragma unroll
        for (int rr = 0; rr < 4; rr++)
            #pragma unroll
            for (int cc = 0; cc < 4; cc++) S[rr][cc] = hadd2(a2[rr][cc]);

        if (kt == qt) {
            #pragma unroll
            for (int rr = 0; rr < 4; rr++) {
                int rl = rg * 4 + rr;
                #pragma unroll
                for (int cc = 0; cc < 4; cc++)
                    if (16 * cc + cg > rl) S[rr][cc] = -1e30f;
            }
        }

        #pragma unroll
        for (int rr = 0; rr < 4; rr++) {
            float pm = fmaxf(fmaxf(S[rr][0], S[rr][1]), fmaxf(S[rr][2], S[rr][3]));
            pm = fmaxf(pm, __shfl_xor_sync(0xffffffffu, pm, 1));
            pm = fmaxf(pm, __shfl_xor_sync(0xffffffffu, pm, 2));
            pm = fmaxf(pm, __shfl_xor_sync(0xffffffffu, pm, 4));
            pm = fmaxf(pm, __shfl_xor_sync(0xffffffffu, pm, 8));
            float mn = fmaxf(m[rr], pm);
            float alpha = __expf(m[rr] - mn);
            float rs = 0.f;
            #pragma unroll
            for (int cc = 0; cc < 4; cc++) {
                S[rr][cc] = __expf(S[rr][cc] - mn);
                rs += S[rr][cc];
            }
            rs += __shfl_xor_sync(0xffffffffu, rs, 1);
            rs += __shfl_xor_sync(0xffffffffu, rs, 2);
            rs += __shfl_xor_sync(0xffffffffu, rs, 4);
            rs += __shfl_xor_sync(0xffffffffu, rs, 8);
            lsum[rr] = lsum[rr] * alpha + rs;
            m[rr] = mn;
            u64 as = splat2(alpha);
            #pragma unroll
            for (int j = 0; j < 4; j++) O2[rr][j] = mul2(O2[rr][j], as);
        }

        {
            int ch = (rg ^ cg) * 4;
            #pragma unroll
            for (int cc = 0; cc < 4; cc++) {
                int s = 16 * cc + cg;
                float* p = St + s * 68 + ch;
                #pragma unroll
                for (int rr = 0; rr < 4; rr++) p[rr] = S[rr][cc];
            }
        }
        __syncthreads();

        #pragma unroll 1
        for (int s = 0; s < 64; s++) {
            float4 p4 = *(const float4*)(St + s * 68 + ((rg ^ (s & 15)) * 4));
            const u64* Vp = Ks2 + s * KROW2 + cg;
            u64 v0 = Vp[0], v1 = Vp[16], v2 = Vp[32], v3 = Vp[48];
            u64 p0 = splat2(p4.x), p1 = splat2(p4.y), p2 = splat2(p4.z), p3 = splat2(p4.w);
            O2[0][0] = fma2(p0, v0, O2[0][0]); O2[0][1] = fma2(p0, v1, O2[0][1]);
            O2[0][2] = fma2(p0, v2, O2[0][2]); O2[0][3] = fma2(p0, v3, O2[0][3]);
            O2[1][0] = fma2(p1, v0, O2[1][0]); O2[1][1] = fma2(p1, v1, O2[1][1]);
            O2[1][2] = fma2(p1, v2, O2[1][2]); O2[1][3] = fma2(p1, v3, O2[1][3]);
            O2[2][0] = fma2(p2, v0, O2[2][0]); O2[2][1] = fma2(p2, v1, O2[2][1]);
            O2[2][2] = fma2(p2, v2, O2[2][2]); O2[2][3] = fma2(p2, v3, O2[2][3]);
            O2[3][0] = fma2(p3, v0, O2[3][0]); O2[3][1] = fma2(p3, v1, O2[3][1]);
            O2[3][2] = fma2(p3, v2, O2[3][2]); O2[3][3] = fma2(p3, v3, O2[3][3]);
        }
    }

    float* Cg = g_ctx + (size_t)b * TT * HID;
    #pragma unroll
    for (int rr = 0; rr < 4; rr++) {
        u64 inv2 = splat2(1.0f / lsum[rr]);
        size_t row = (size_t)qrow0 + rg * 4 + rr;
        #pragma unroll
        for (int j = 0; j < 4; j++) {
            float2 p = unpack2(mul2(O2[rr][j], inv2));
            *(float2*)(Cg + row * HID + 2 * cg + 32 * j) = p;
        }
    }
}

// ---------------------------------------------------------------------------
// FC to vocab: 4 row-tiles (4x16 rows) per block, fwt loaded ONCE per block.
// ---------------------------------------------------------------------------
__global__ __launch_bounds__(256, 1)
void fc_kernel(const float* __restrict__ fc_w, const float* __restrict__ fc_b,
               float* __restrict__ out) {
    extern __shared__ float smf[];
    float* fwt = smf;                 // [k=256][c stride 56]
    float* xst = smf + 256 * 56;      // [k=256][r stride 20]

    const int t = threadIdx.x;
    const int c  = t & 63;
    const int rg = t >> 6;

    for (int idx = t; idx < VOCAB * 256; idx += 256) {
        int cc = idx >> 8, k = idx & 255;
        fwt[k * 56 + cc] = fc_w[idx];
    }
    const float bb = (c < VOCAB) ? fc_b[c] : 0.f;

    #pragma unroll 1
    for (int part = 0; part < 4; part++) {
        const size_t rowbase = (size_t)blockIdx.x * 64 + part * 16;
        __syncthreads();
        for (int idx = t; idx < 16 * 256; idx += 256) {
            int r = idx >> 8, k = idx & 255;
            size_t row = rowbase + r;
            float v = (k < HID) ? g_outs[row * HID + k] : g_ctx[row * HID + (k - HID)];
            xst[k * 20 + r] = v;
        }
        __syncthreads();

        if (c < VOCAB) {
            float a0 = 0.f, a1 = 0.f, a2 = 0.f, a3 = 0.f;
            #pragma unroll 4
            for (int k = 0; k < 256; k++) {
                float4 x4 = *(const float4*)(xst + k * 20 + rg * 4);
                float wv = fwt[k * 56 + c];
                a0 = fmaf(x4.x, wv, a0);
                a1 = fmaf(x4.y, wv, a1);
                a2 = fmaf(x4.z, wv, a2);
                a3 = fmaf(x4.w, wv, a3);
            }
            out[(rowbase + rg * 4 + 0) * VOCAB + c] = a0 + bb;
            out[(rowbase + rg * 4 + 1) * VOCAB + c] = a1 + bb;
            out[(rowbase + rg * 4 + 2) * VOCAB + c] = a2 + bb;
            out[(rowbase + rg * 4 + 3) * VOCAB + c] = a3 + bb;
        }
    }
}

// ---------------------------------------------------------------------------
extern "C" void kernel_launch(void* const* d_in, const int* in_sizes, int n_in,
                              void* d_out, int out_size) {
    const int*   x      = (const int*)  d_in[0];
    const float* emb    = (const float*)d_in[1];
    const float* w_ih0  = (const float*)d_in[2];
    const float* b_ih0  = (const float*)d_in[3];
    const float* w_hh0  = (const float*)d_in[4];
    const float* b_hh0  = (const float*)d_in[5];
    const float* w_ih1  = (const float*)d_in[6];
    const float* b_ih1  = (const float*)d_in[7];
    const float* w_hh1  = (const float*)d_in[8];
    const float* b_hh1  = (const float*)d_in[9];
    const float* attn_w = (const float*)d_in[10];
    const float* attn_b = (const float*)d_in[11];
    const float* fc_w   = (const float*)d_in[12];
    const float* fc_b   = (const float*)d_in[13];
    float* out = (float*)d_out;

    const int QSMEM = (128 * 132 + 128 * 68) * 4;      // 102400
    const int ASMEM = (2 * 64 * KROW + 64 * 68) * 4;   // 83968
    const int FSMEM = (256 * 56 + 256 * 20) * 4;       // 77824
    cudaFuncSetAttribute((const void*)q_kernel,
                         cudaFuncAttributeMaxDynamicSharedMemorySize, QSMEM);
    cudaFuncSetAttribute((const void*)attn_kernel,
                         cudaFuncAttributeMaxDynamicSharedMemorySize, ASMEM);
    cudaFuncSetAttribute((const void*)fc_kernel,
                         cudaFuncAttributeMaxDynamicSharedMemorySize, FSMEM);

    tab0_kernel<<<VOCAB, HID>>>(emb, w_ih0, b_ih0, b_hh0);
    dummy_kernel<<<1, 32>>>();                          // shim: rnn -> capture idx 3
    dummy_kernel<<<1, 32>>>();
    rnn_kernel<<<BB, 384>>>(x, w_hh0, w_ih1, b_ih1, w_hh1, b_hh1);
    q_kernel<<<(BB * TT) / 128, 256, QSMEM>>>(attn_w, attn_b);
    attn_kernel<<<dim3(BB, 16), 256, ASMEM>>>();        // LPT: qt = 15 - blockIdx.y
    fc_kernel<<<(BB * TT) / 64, 256, FSMEM>>>(fc_w, fc_b, out);
}

// round 17
// speedup vs baseline: 1.7998x; 1.0066x over previous
#include <cuda_runtime.h>
#include <math.h>
#include <stddef.h>

#define BB    64
#define TT    1024
#define VOCAB 55
#define EMBED 64
#define HID   128

typedef unsigned long long u64;

__device__ float g_outs[BB * TT * HID];
__device__ float g_q   [BB * TT * HID];
__device__ float g_ctx [BB * TT * HID];
__device__ float g_tab0[VOCAB * HID];

// Packed f32x2 helpers
__device__ __forceinline__ u64 fma2(u64 a, u64 b, u64 c) {
    u64 d; asm("fma.rn.f32x2 %0, %1, %2, %3;" : "=l"(d) : "l"(a), "l"(b), "l"(c));
    return d;
}
__device__ __forceinline__ u64 add2(u64 a, u64 b) {
    u64 d; asm("add.rn.f32x2 %0, %1, %2;" : "=l"(d) : "l"(a), "l"(b));
    return d;
}
__device__ __forceinline__ u64 mul2(u64 a, u64 b) {
    u64 d; asm("mul.rn.f32x2 %0, %1, %2;" : "=l"(d) : "l"(a), "l"(b));
    return d;
}
__device__ __forceinline__ u64 splat2(float v) {
    u64 r; asm("mov.b64 %0, {%1, %1};" : "=l"(r) : "f"(v));
    return r;
}
__device__ __forceinline__ float2 unpack2(u64 v) {
    float lo, hi; asm("mov.b64 {%0, %1}, %2;" : "=f"(lo), "=f"(hi) : "l"(v));
    return make_float2(lo, hi);
}
__device__ __forceinline__ float hadd2(u64 v) {
    float2 p = unpack2(v); return p.x + p.y;
}
__device__ __forceinline__ float tanh_fast(float x) {
    float e = __expf(2.0f * x);
    return 1.0f - __fdividef(2.0f, e + 1.0f);
}

#define BAR_SYNC(id, cnt)   asm volatile("bar.sync %0, %1;"   :: "r"(id), "r"(cnt) : "memory")
#define BAR_ARRIVE(id, cnt) asm volatile("bar.arrive %0, %1;" :: "r"(id), "r"(cnt) : "memory")

// ---------------------------------------------------------------------------
__global__ void dummy_kernel() {}   // launch-index shim so ncu captures rnn

// ---------------------------------------------------------------------------
__global__ void tab0_kernel(const float* __restrict__ emb,
                            const float* __restrict__ w_ih0,
                            const float* __restrict__ b_ih0,
                            const float* __restrict__ b_hh0) {
    __shared__ float es[EMBED];
    int v = blockIdx.x;
    int i = threadIdx.x;
    if (i < EMBED) es[i] = emb[v * EMBED + i];
    __syncthreads();
    float acc = b_ih0[i] + b_hh0[i];
    #pragma unroll
    for (int e = 0; e < EMBED; e++)
        acc += es[e] * w_ih0[i * EMBED + e];
    g_tab0[v * HID + i] = acc;
}

// ---------------------------------------------------------------------------
// 3-group warp-specialized RNN scan. 384 thr/block, one block per batch.
//   A (0..127):   layer0 producer; lead <=2 over C.
//   C (128..255): uv(t) = W_ih1 h0(t) + biases; lead <=4 over D (4-slot ring).
//   D (256..383): serial h1(t) = tanh(W_hh1 h1(t-1) + uv(t)); 1 thr/output.
// Barrier map (rule: #IDs >= max lead of the un-gated side, both directions):
//   id 1      A-early (st<2), cnt 128
//   ids 2-3   dataAC  2+(st&1), cnt 256   | ids 4-5   credCA 4+(st&1) (A skips 2)
//   ids 6-9   dataCD  6+(st&3), cnt 256   | ids 10-13 credDC 10+(st&3) (C skips 4)
// ---------------------------------------------------------------------------
__global__ __launch_bounds__(384, 1)
void rnn_kernel(const int*   __restrict__ x,
                const float* __restrict__ w_hh0,
                const float* __restrict__ w_ih1,
                const float* __restrict__ b_ih1,
                const float* __restrict__ w_hh1,
                const float* __restrict__ b_hh1) {
    __shared__ float tab0s[VOCAB * HID];
    __shared__ int   xs[TT];
    __shared__ __align__(16) float h0b[4][HID];
    __shared__ __align__(16) float uvb[4][HID];
    __shared__ __align__(16) float h1b[2][HID];

    const int b = blockIdx.x;
    const int t = threadIdx.x;

    for (int idx = t; idx < VOCAB * HID; idx += 384) tab0s[idx] = g_tab0[idx];
    for (int idx = t; idx < TT;          idx += 384) xs[idx]    = x[b * TT + idx];
    if (t < HID) {
        h0b[0][t] = 0.f; h0b[1][t] = 0.f; h0b[2][t] = 0.f; h0b[3][t] = 0.f;
        h1b[0][t] = 0.f; h1b[1][t] = 0.f;
    }

    float* outp = g_outs + (size_t)b * TT * HID;

    if (t < 128) {
        // ================= Group A: layer0 producer =================
        u64 wreg[64];
        {
            const ulonglong2* wp = (const ulonglong2*)(w_hh0 + t * HID);
            #pragma unroll
            for (int m = 0; m < 32; m++) { ulonglong2 v = wp[m]; wreg[2*m] = v.x; wreg[2*m+1] = v.y; }
        }
        __syncthreads();
        #pragma unroll 1
        for (int st = 0; st < TT; st++) {
            const int sl = st & 3, prev = (st - 1) & 3, p1 = st & 1;
            if (st >= 2) BAR_SYNC(4 + p1, 256);          // C consumed h0 @ st-2
            const float tb = tab0s[xs[st] * HID + t];
            const ulonglong2* hp = (const ulonglong2*)(&h0b[prev][0]);
            u64 a0 = 0, a1 = 0, a2 = 0, a3 = 0;
            #pragma unroll
            for (int m = 0; m < 16; m++) {
                ulonglong2 va = hp[2*m], vb = hp[2*m+1];
                a0 = fma2(va.x, wreg[4*m],     a0);
                a1 = fma2(va.y, wreg[4*m + 1], a1);
                a2 = fma2(vb.x, wreg[4*m + 2], a2);
                a3 = fma2(vb.y, wreg[4*m + 3], a3);
            }
            float acc = hadd2(add2(add2(a0, a1), add2(a2, a3)));
            float h0n = tanh_fast(acc + tb);
            h0b[sl][t] = h0n;
            BAR_ARRIVE(2 + p1, 256);                     // h0(st) ready for C
            if (st < 2) BAR_SYNC(1, 128);                // early A ordering
        }
    } else if (t < 256) {
        // ================= Group C: uv = W_ih1 h0 + biases (off-chain) ======
        const int i = t - 128;
        u64 wreg[64];
        {
            const ulonglong2* wp = (const ulonglong2*)(w_ih1 + i * HID);
            #pragma unroll
            for (int m = 0; m < 32; m++) { ulonglong2 v = wp[m]; wreg[2*m] = v.x; wreg[2*m+1] = v.y; }
        }
        const float c1 = b_ih1[i] + b_hh1[i];
        __syncthreads();
        #pragma unroll 1
        for (int st = 0; st < TT; st++) {
            const int sl = st & 3, p1 = st & 1;
            BAR_SYNC(2 + p1, 256);                       // wait h0(st)
            if (st >= 4) BAR_SYNC(10 + sl, 256);         // D consumed uvb[sl] @ st-4
            const ulonglong2* hp = (const ulonglong2*)(&h0b[sl][0]);
            u64 a0 = 0, a1 = 0, a2 = 0, a3 = 0;
            #pragma unroll
            for (int m = 0; m < 16; m++) {
                ulonglong2 va = hp[2*m], vb = hp[2*m+1];
                a0 = fma2(va.x, wreg[4*m],     a0);
                a1 = fma2(va.y, wreg[4*m + 1], a1);
                a2 = fma2(vb.x, wreg[4*m + 2], a2);
                a3 = fma2(vb.y, wreg[4*m + 3], a3);
            }
            BAR_ARRIVE(4 + p1, 256);                     // credit h0 to A
            float acc = hadd2(add2(add2(a0, a1), add2(a2, a3)));
            uvb[sl][i] = acc + c1;                       // 4-slot ring
            BAR_ARRIVE(6 + sl, 256);                     // publish uv(st)
        }
    } else {
        // ================= Group D: serial h1 recurrence ====================
        const int i = t - 256;                           // one output per thread
        u64 wreg[64];                                    // full w_hh1 row i
        {
            const ulonglong2* wp = (const ulonglong2*)(w_hh1 + i * HID);
            #pragma unroll
            for (int m = 0; m < 32; m++) { ulonglong2 v = wp[m]; wreg[2*m] = v.x; wreg[2*m+1] = v.y; }
        }
        __syncthreads();
        #pragma unroll 1
        for (int st = 0; st < TT; st++) {
            const int sl = st & 3, s2 = st & 1;
            BAR_SYNC(6 + sl, 256);                       // wait uv(st); orders h1b too
            const float uvv = uvb[sl][i];                // ready LDS, overlaps dot
            const ulonglong2* hp = (const ulonglong2*)(&h1b[s2 ^ 1][0]);
            u64 a0 = 0, a1 = 0, a2 = 0, a3 = 0;
            #pragma unroll
            for (int m = 0; m < 16; m++) {
                ulonglong2 va = hp[2*m], vb = hp[2*m+1];
                a0 = fma2(va.x, wreg[4*m],     a0);
                a1 = fma2(va.y, wreg[4*m + 1], a1);
                a2 = fma2(vb.x, wreg[4*m + 2], a2);
                a3 = fma2(vb.y, wreg[4*m + 3], a3);
            }
            float acc = hadd2(add2(add2(a0, a1), add2(a2, a3)));
            float tot = acc + uvv;                       // uv consumed here
            BAR_ARRIVE(10 + sl, 256);                    // credit uvb[sl]
            float h1n = tanh_fast(tot);
            h1b[s2][i] = h1n;
            outp[st * HID + i] = h1n;
            // next step's dataCD sync orders h1b write->read within D
        }
    }
}

// ---------------------------------------------------------------------------
// Q projection: 2 row-tiles (2x64 rows) per block, wt loaded ONCE per block.
// ---------------------------------------------------------------------------
__global__ __launch_bounds__(256, 1)
void q_kernel(const float* __restrict__ attn_w, const float* __restrict__ attn_b) {
    extern __shared__ float smq[];
    float* wt  = smq;                 // [k=128][i stride 132]
    float* ost = smq + 128 * 132;     // [k=128][r stride 68]
    __shared__ float bs[HID];

    const int t = threadIdx.x;
    const int rg = t >> 4, cg = t & 15;

    for (int idx = t; idx < HID * HID; idx += 256) {
        int i = idx >> 7, k = idx & 127;
        wt[k * 132 + i] = attn_w[idx];
    }
    if (t < HID) bs[t] = attn_b[t];

    #pragma unroll 1
    for (int half = 0; half < 2; half++) {
        const size_t rowbase = (size_t)blockIdx.x * 128 + half * 64;
        __syncthreads();
        for (int idx = t; idx < 64 * HID; idx += 256) {
            int r = idx >> 7, k = idx & 127;
            ost[k * 68 + r] = g_outs[(rowbase + r) * HID + k];
        }
        __syncthreads();

        u64 acc[4][4];
        #pragma unroll
        for (int rr = 0; rr < 4; rr++)
            #pragma unroll
            for (int c = 0; c < 4; c++) acc[rr][c] = 0ull;

        #pragma unroll 2
        for (int k = 0; k < HID; k++) {
            float4 q4 = *(const float4*)(ost + k * 68 + rg * 4);
            ulonglong2 w0 = *(const ulonglong2*)(wt + k * 132 + cg * 8);
            ulonglong2 w1 = *(const ulonglong2*)(wt + k * 132 + cg * 8 + 4);
            float qv[4] = {q4.x, q4.y, q4.z, q4.w};
            #pragma unroll
            for (int rr = 0; rr < 4; rr++) {
                u64 qs = splat2(qv[rr]);
                acc[rr][0] = fma2(qs, w0.x, acc[rr][0]);
                acc[rr][1] = fma2(qs, w0.y, acc[rr][1]);
                acc[rr][2] = fma2(qs, w1.x, acc[rr][2]);
                acc[rr][3] = fma2(qs, w1.y, acc[rr][3]);
            }
        }

        #pragma unroll
        for (int rr = 0; rr < 4; rr++) {
            size_t row = rowbase + rg * 4 + rr;
            float o[8];
            #pragma unroll
            for (int c = 0; c < 4; c++) {
                float2 p = unpack2(acc[rr][c]);
                o[2*c]   = p.x + bs[cg * 8 + 2*c];
                o[2*c+1] = p.y + bs[cg * 8 + 2*c + 1];
            }
            *(float4*)(g_q + row * HID + cg * 8)     = make_float4(o[0], o[1], o[2], o[3]);
            *(float4*)(g_q + row * HID + cg * 8 + 4) = make_float4(o[4], o[5], o[6], o[7]);
        }
    }
}

// ---------------------------------------------------------------------------
// Flash attention, 2 CTAs/SM, LPT ordering (unchanged).
// ---------------------------------------------------------------------------
#define KROW  130
#define KROW2 65

__global__ __launch_bounds__(256, 2)
void attn_kernel() {
    extern __shared__ float sma[];
    float* Qs = sma;                     // [64][130]
    float* Ks = sma + 64 * KROW;         // [64][130]
    float* St = sma + 2 * 64 * KROW;     // [64][68], xor-swizzled 4-row chunks
    u64* Qs2 = (u64*)Qs;
    u64* Ks2 = (u64*)Ks;

    const int qt = 15 - blockIdx.y;      // LPT: heaviest tiles first
    const int b  = blockIdx.x;
    const int t  = threadIdx.x;
    const int rg = t >> 4, cg = t & 15;
    const int qrow0 = qt * 64;
    const float* Qg = g_q    + (size_t)b * TT * HID;
    const float* Og = g_outs + (size_t)b * TT * HID;

    {
        const u64 sc2 = splat2(0.08838834764831845f);
        const u64* Qg2 = (const u64*)Qg;
        #pragma unroll
        for (int j = 0; j < 16; j++) {
            int idx2 = t + 256 * j;
            int r = idx2 >> 6, h2 = idx2 & 63;
            u64 v = Qg2[(size_t)(qrow0 + r) * (HID/2) + h2];
            Qs2[r * KROW2 + h2] = mul2(v, sc2);
        }
    }

    float m[4], lsum[4];
    u64 O2[4][4];
    #pragma unroll
    for (int rr = 0; rr < 4; rr++) {
        m[rr] = -1e30f; lsum[rr] = 0.f;
        #pragma unroll
        for (int j = 0; j < 4; j++) O2[rr][j] = 0ull;
    }

    const int nkt = qt + 1;
    for (int kt = 0; kt < nkt; kt++) {
        __syncthreads();
        {
            const u64* Og2 = (const u64*)Og;
            #pragma unroll
            for (int j = 0; j < 16; j++) {
                int idx2 = t + 256 * j;
                int s = idx2 >> 6, h2 = idx2 & 63;
                Ks2[s * KROW2 + h2] = Og2[(size_t)(kt * 64 + s) * (HID/2) + h2];
            }
        }
        __syncthreads();

        u64 a2[4][4];
        #pragma unroll
        for (int rr = 0; rr < 4; rr++)
            #pragma unroll
            for (int cc = 0; cc < 4; cc++) a2[rr][cc] = 0ull;
        {
            const u64* Qp = Qs2 + (rg * 4) * KROW2;
            const u64* Kp = Ks2 + cg * KROW2;
            #pragma unroll 1
            for (int h2 = 0; h2 < 64; h2++) {
                u64 q0 = Qp[h2], q1 = Qp[KROW2 + h2], q2 = Qp[2*KROW2 + h2], q3 = Qp[3*KROW2 + h2];
                u64 k0 = Kp[h2], k1 = Kp[16*KROW2 + h2], k2 = Kp[32*KROW2 + h2], k3 = Kp[48*KROW2 + h2];
                a2[0][0] = fma2(q0, k0, a2[0][0]); a2[0][1] = fma2(q0, k1, a2[0][1]);
                a2[0][2] = fma2(q0, k2, a2[0][2]); a2[0][3] = fma2(q0, k3, a2[0][3]);
                a2[1][0] = fma2(q1, k0, a2[1][0]); a2[1][1] = fma2(q1, k1, a2[1][1]);
                a2[1][2] = fma2(q1, k2, a2[1][2]); a2[1][3] = fma2(q1, k3, a2[1][3]);
                a2[2][0] = fma2(q2, k0, a2[2][0]); a2[2][1] = fma2(q2, k1, a2[2][1]);
                a2[2][2] = fma2(q2, k2, a2[2][2]); a2[2][3] = fma2(q2, k3, a2[2][3]);
                a2[3][0] = fma2(q3, k0, a2[3][0]); a2[3][1] = fma2(q3, k1, a2[3][1]);
                a2[3][2] = fma2(q3, k2, a2[3][2]); a2[3][3] = fma2(q3, k3, a2[3][3]);
            }
        }

        float S[4][4];
        #pragma unroll
        for (int rr = 0; rr < 4; rr++)
            #pragma unroll
            for (int cc = 0; cc < 4; cc++) S[rr][cc] = hadd2(a2[rr][cc]);

        if (kt == qt) {
            #pragma unroll
            for (int rr = 0; rr < 4; rr++) {
                int rl = rg * 4 + rr;
                #pragma unroll
                for (int cc = 0; cc < 4; cc++)
                    if (16 * cc + cg > rl) S[rr][cc] = -1e30f;
            }
        }

        #pragma unroll
        for (int rr = 0; rr < 4; rr++) {
            float pm = fmaxf(fmaxf(S[rr][0], S[rr][1]), fmaxf(S[rr][2], S[rr][3]));
            pm = fmaxf(pm, __shfl_xor_sync(0xffffffffu, pm, 1));
            pm = fmaxf(pm, __shfl_xor_sync(0xffffffffu, pm, 2));
            pm = fmaxf(pm, __shfl_xor_sync(0xffffffffu, pm, 4));
            pm = fmaxf(pm, __shfl_xor_sync(0xffffffffu, pm, 8));
            float mn = fmaxf(m[rr], pm);
            float alpha = __expf(m[rr] - mn);
            float rs = 0.f;
            #pragma unroll
            for (int cc = 0; cc < 4; cc++) {
                S[rr][cc] = __expf(S[rr][cc] - mn);
                rs += S[rr][cc];
            }
            rs += __shfl_xor_sync(0xffffffffu, rs, 1);
            rs += __shfl_xor_sync(0xffffffffu, rs, 2);
            rs += __shfl_xor_sync(0xffffffffu, rs, 4);
            rs += __shfl_xor_sync(0xffffffffu, rs, 8);
            lsum[rr] = lsum[rr] * alpha + rs;
            m[rr] = mn;
            u64 as = splat2(alpha);
            #pragma unroll
            for (int j = 0; j < 4; j++) O2[rr][j] = mul2(O2[rr][j], as);
        }

        {
            int ch = (rg ^ cg) * 4;
            #pragma unroll
            for (int cc = 0; cc < 4; cc++) {
                int s = 16 * cc + cg;
                float* p = St + s * 68 + ch;
                #pragma unroll
                for (int rr = 0; rr < 4; rr++) p[rr] = S[rr][cc];
            }
        }
        __syncthreads();

        #pragma unroll 1
        for (int s = 0; s < 64; s++) {
            float4 p4 = *(const float4*)(St + s * 68 + ((rg ^ (s & 15)) * 4));
            const u64* Vp = Ks2 + s * KROW2 + cg;
            u64 v0 = Vp[0], v1 = Vp[16], v2 = Vp[32], v3 = Vp[48];
            u64 p0 = splat2(p4.x), p1 = splat2(p4.y), p2 = splat2(p4.z), p3 = splat2(p4.w);
            O2[0][0] = fma2(p0, v0, O2[0][0]); O2[0][1] = fma2(p0, v1, O2[0][1]);
            O2[0][2] = fma2(p0, v2, O2[0][2]); O2[0][3] = fma2(p0, v3, O2[0][3]);
            O2[1][0] = fma2(p1, v0, O2[1][0]); O2[1][1] = fma2(p1, v1, O2[1][1]);
            O2[1][2] = fma2(p1, v2, O2[1][2]); O2[1][3] = fma2(p1, v3, O2[1][3]);
            O2[2][0] = fma2(p2, v0, O2[2][0]); O2[2][1] = fma2(p2, v1, O2[2][1]);
            O2[2][2] = fma2(p2, v2, O2[2][2]); O2[2][3] = fma2(p2, v3, O2[2][3]);
            O2[3][0] = fma2(p3, v0, O2[3][0]); O2[3][1] = fma2(p3, v1, O2[3][1]);
            O2[3][2] = fma2(p3, v2, O2[3][2]); O2[3][3] = fma2(p3, v3, O2[3][3]);
        }
    }

    float* Cg = g_ctx + (size_t)b * TT * HID;
    #pragma unroll
    for (int rr = 0; rr < 4; rr++) {
        u64 inv2 = splat2(1.0f / lsum[rr]);
        size_t row = (size_t)qrow0 + rg * 4 + rr;
        #pragma unroll
        for (int j = 0; j < 4; j++) {
            float2 p = unpack2(mul2(O2[rr][j], inv2));
            *(float2*)(Cg + row * HID + 2 * cg + 32 * j) = p;
        }
    }
}

// ---------------------------------------------------------------------------
// FC to vocab: 4 row-tiles (4x16 rows) per block, fwt loaded ONCE per block.
// ---------------------------------------------------------------------------
__global__ __launch_bounds__(256, 1)
void fc_kernel(const float* __restrict__ fc_w, const float* __restrict__ fc_b,
               float* __restrict__ out) {
    extern __shared__ float smf[];
    float* fwt = smf;                 // [k=256][c stride 56]
    float* xst = smf + 256 * 56;      // [k=256][r stride 20]

    const int t = threadIdx.x;
    const int c  = t & 63;
    const int rg = t >> 6;

    for (int idx = t; idx < VOCAB * 256; idx += 256) {
        int cc = idx >> 8, k = idx & 255;
        fwt[k * 56 + cc] = fc_w[idx];
    }
    const float bb = (c < VOCAB) ? fc_b[c] : 0.f;

    #pragma unroll 1
    for (int part = 0; part < 4; part++) {
        const size_t rowbase = (size_t)blockIdx.x * 64 + part * 16;
        __syncthreads();
        for (int idx = t; idx < 16 * 256; idx += 256) {
            int r = idx >> 8, k = idx & 255;
            size_t row = rowbase + r;
            float v = (k < HID) ? g_outs[row * HID + k] : g_ctx[row * HID + (k - HID)];
            xst[k * 20 + r] = v;
        }
        __syncthreads();

        if (c < VOCAB) {
            float a0 = 0.f, a1 = 0.f, a2 = 0.f, a3 = 0.f;
            #pragma unroll 4
            for (int k = 0; k < 256; k++) {
                float4 x4 = *(const float4*)(xst + k * 20 + rg * 4);
                float wv = fwt[k * 56 + c];
                a0 = fmaf(x4.x, wv, a0);
                a1 = fmaf(x4.y, wv, a1);
                a2 = fmaf(x4.z, wv, a2);
                a3 = fmaf(x4.w, wv, a3);
            }
            out[(rowbase + rg * 4 + 0) * VOCAB + c] = a0 + bb;
            out[(rowbase + rg * 4 + 1) * VOCAB + c] = a1 + bb;
            out[(rowbase + rg * 4 + 2) * VOCAB + c] = a2 + bb;
            out[(rowbase + rg * 4 + 3) * VOCAB + c] = a3 + bb;
        }
    }
}

// ---------------------------------------------------------------------------
extern "C" void kernel_launch(void* const* d_in, const int* in_sizes, int n_in,
                              void* d_out, int out_size) {
    const int*   x      = (const int*)  d_in[0];
    const float* emb    = (const float*)d_in[1];
    const float* w_ih0  = (const float*)d_in[2];
    const float* b_ih0  = (const float*)d_in[3];
    const float* w_hh0  = (const float*)d_in[4];
    const float* b_hh0  = (const float*)d_in[5];
    const float* w_ih1  = (const float*)d_in[6];
    const float* b_ih1  = (const float*)d_in[7];
    const float* w_hh1  = (const float*)d_in[8];
    const float* b_hh1  = (const float*)d_in[9];
    const float* attn_w = (const float*)d_in[10];
    const float* attn_b = (const float*)d_in[11];
    const float* fc_w   = (const float*)d_in[12];
    const float* fc_b   = (const float*)d_in[13];
    float* out = (float*)d_out;

    const int QSMEM = (128 * 132 + 128 * 68) * 4;      // 102400
    const int ASMEM = (2 * 64 * KROW + 64 * 68) * 4;   // 83968
    const int FSMEM = (256 * 56 + 256 * 20) * 4;       // 77824
    cudaFuncSetAttribute((const void*)q_kernel,
                         cudaFuncAttributeMaxDynamicSharedMemorySize, QSMEM);
    cudaFuncSetAttribute((const void*)attn_kernel,
                         cudaFuncAttributeMaxDynamicSharedMemorySize, ASMEM);
    cudaFuncSetAttribute((const void*)fc_kernel,
                         cudaFuncAttributeMaxDynamicSharedMemorySize, FSMEM);

    tab0_kernel<<<VOCAB, HID>>>(emb, w_ih0, b_ih0, b_hh0);
    dummy_kernel<<<1, 32>>>();                          // shim: rnn -> capture idx 3
    dummy_kernel<<<1, 32>>>();
    rnn_kernel<<<BB, 384>>>(x, w_hh0, w_ih1, b_ih1, w_hh1, b_hh1);
    q_kernel<<<(BB * TT) / 128, 256, QSMEM>>>(attn_w, attn_b);
    attn_kernel<<<dim3(BB, 16), 256, ASMEM>>>();        // LPT: qt = 15 - blockIdx.y
    fc_kernel<<<(BB * TT) / 64, 256, FSMEM>>>(fc_w, fc_b, out);
}